// round 1
// baseline (speedup 1.0000x reference)
#include <cuda_runtime.h>
#include <math_constants.h>

// Problem constants
#define BB 256
#define CC 8
#define MM 16
#define NN 4096
#define CM 128      // CC*MM
#define LEN_R 64
#define LEN_D 64

// Kernel 1: outputs[b,n] = sum_k x[b,k,n] * W[k]   (k = c*M+m, 128 terms)
// Each thread computes 4 consecutive n (float4). Block = 256 threads -> 1024 n.
// grid = (NN/1024, BB).
__global__ __launch_bounds__(256) void conv_kernel(
    const float* __restrict__ x, const float* __restrict__ W,
    float* __restrict__ out)
{
    __shared__ float w[CM];
    int t = threadIdx.x;
    if (t < CM) w[t] = W[t];
    __syncthreads();

    int b  = blockIdx.y;
    int n4 = blockIdx.x * blockDim.x + t;          // index into N/4 float4 lanes
    const float4* xb = reinterpret_cast<const float4*>(x) + (size_t)b * CM * (NN / 4);

    float4 acc = make_float4(0.f, 0.f, 0.f, 0.f);
    #pragma unroll 16
    for (int k = 0; k < CM; k++) {
        float4 v = xb[(size_t)k * (NN / 4) + n4];
        float wk = w[k];
        acc.x += v.x * wk;
        acc.y += v.y * wk;
        acc.z += v.z * wk;
        acc.w += v.w * wk;
    }
    reinterpret_cast<float4*>(out + (size_t)b * NN)[n4] = acc;
}

// Kernel 2: per-b argmax over N (first occurrence), then tail writes.
// tail layout (after outputs): d[B], r[B], d[B]  (pytree leaves of (outputs, d, (r,d)))
__global__ __launch_bounds__(256) void argmax_tail_kernel(
    const float* __restrict__ out,
    const float* __restrict__ r_target,
    const float* __restrict__ d_target,
    float* __restrict__ tail)
{
    int b = blockIdx.x;
    const float* row = out + (size_t)b * NN;
    int t = threadIdx.x;

    float best = -CUDART_INF_F;
    int bidx = NN;  // sentinel larger than any valid index
    for (int i = t; i < NN; i += 256) {
        float v = row[i];
        if (v > best || (v == best && i < bidx)) { best = v; bidx = i; }
    }

    __shared__ float sv[256];
    __shared__ int   si[256];
    sv[t] = best; si[t] = bidx;
    __syncthreads();
    #pragma unroll
    for (int s = 128; s > 0; s >>= 1) {
        if (t < s) {
            if (sv[t + s] > sv[t] || (sv[t + s] == sv[t] && si[t + s] < si[t])) {
                sv[t] = sv[t + s]; si[t] = si[t + s];
            }
        }
        __syncthreads();
    }

    if (t == 0) {
        int idx = si[0];
        int ri = idx / LEN_R;
        int di = idx - (idx / LEN_R) * LEN_D;   // == idx % 64 here
        // .astype(index.dtype) truncates toward zero; replicate via int cast.
        float rv = (float)(long long)(r_target[ri]);
        float dv = (float)(long long)(d_target[di]);
        tail[b]           = dv;  // leaf 2: d
        tail[BB + b]      = rv;  // leaf 3: r  (output tuple first element)
        tail[2 * BB + b]  = dv;  // leaf 4: d  (output tuple second element)
    }
}

extern "C" void kernel_launch(void* const* d_in, const int* in_sizes, int n_in,
                              void* d_out, int out_size)
{
    const float* x  = (const float*)d_in[0];  // [B, C, M, N]
    const float* W  = (const float*)d_in[1];  // [1, C, M, 1] -> 128 floats
    const float* rt = (const float*)d_in[2];  // [64]
    const float* dt = (const float*)d_in[3];  // [64]
    float* out = (float*)d_out;

    dim3 grid(NN / (256 * 4), BB);
    conv_kernel<<<grid, 256>>>(x, W, out);
    argmax_tail_kernel<<<BB, 256>>>(out, rt, dt, out + (size_t)BB * NN);
}

// round 2
// speedup vs baseline: 1.0553x; 1.0553x over previous
#include <cuda_runtime.h>
#include <math_constants.h>

// Problem constants
#define BB 256
#define CC 8
#define MM 16
#define NN 4096
#define CM 128      // CC*MM
#define LEN_R 64
#define LEN_D 64
#define NBLK 4      // blocks along N per b (NN / 1024)

// Per-(b, n-block) partial argmax scratch (device globals: allocation-free).
__device__ float g_pmax[BB][NBLK];
__device__ int   g_pidx[BB][NBLK];

// Kernel 1: outputs[b,n] = sum_k x[b,k,n] * W[k]  (k = c*M+m, 128 terms)
// Each thread computes 4 consecutive n (float4); block covers 1024 n of one b.
// Fused: block-level partial argmax (first-occurrence tie-break) -> scratch.
__global__ __launch_bounds__(256) void conv_kernel(
    const float* __restrict__ x, const float* __restrict__ W,
    float* __restrict__ out)
{
    __shared__ float w[CM];
    int t = threadIdx.x;
    if (t < CM) w[t] = W[t];
    __syncthreads();

    int b  = blockIdx.y;
    int n4 = blockIdx.x * blockDim.x + t;          // float4 lane index in N/4
    const float4* xb = reinterpret_cast<const float4*>(x) + (size_t)b * CM * (NN / 4);

    float4 acc = make_float4(0.f, 0.f, 0.f, 0.f);
    #pragma unroll 16
    for (int k = 0; k < CM; k++) {
        float4 v = xb[(size_t)k * (NN / 4) + n4];
        float wk = w[k];
        acc.x += v.x * wk;
        acc.y += v.y * wk;
        acc.z += v.z * wk;
        acc.w += v.w * wk;
    }
    reinterpret_cast<float4*>(out + (size_t)b * NN)[n4] = acc;

    // Thread-local argmax over the 4 lanes (ascending index, strict > keeps first).
    int nbase = n4 * 4;
    float best = acc.x; int bidx = nbase;
    if (acc.y > best) { best = acc.y; bidx = nbase + 1; }
    if (acc.z > best) { best = acc.z; bidx = nbase + 2; }
    if (acc.w > best) { best = acc.w; bidx = nbase + 3; }

    // Block reduction (first occurrence on ties).
    __shared__ float sv[256];
    __shared__ int   si[256];
    sv[t] = best; si[t] = bidx;
    __syncthreads();
    #pragma unroll
    for (int s = 128; s > 0; s >>= 1) {
        if (t < s) {
            float ov = sv[t + s]; int oi = si[t + s];
            if (ov > sv[t] || (ov == sv[t] && oi < si[t])) { sv[t] = ov; si[t] = oi; }
        }
        __syncthreads();
    }
    if (t == 0) {
        g_pmax[b][blockIdx.x] = sv[0];
        g_pidx[b][blockIdx.x] = si[0];
    }
}

// Kernel 2: one block, thread b reduces its NBLK partials and writes the tail.
// tail layout (after outputs): d[B], r[B], d[B]  (pytree leaves of (outputs, d, (r,d)))
__global__ __launch_bounds__(256) void tail_kernel(
    const float* __restrict__ r_target,
    const float* __restrict__ d_target,
    float* __restrict__ tail)
{
    int b = threadIdx.x;
    float best = g_pmax[b][0];
    int   bidx = g_pidx[b][0];
    #pragma unroll
    for (int j = 1; j < NBLK; j++) {
        float v = g_pmax[b][j]; int i = g_pidx[b][j];
        if (v > best || (v == best && i < bidx)) { best = v; bidx = i; }
    }
    int ri = bidx / LEN_R;
    int di = bidx - (bidx / LEN_R) * LEN_D;
    // .astype(index.dtype) truncates toward zero; replicate via int cast.
    float rv = (float)(long long)(r_target[ri]);
    float dv = (float)(long long)(d_target[di]);
    tail[b]          = dv;  // leaf 2: d
    tail[BB + b]     = rv;  // leaf 3: r
    tail[2 * BB + b] = dv;  // leaf 4: d
}

extern "C" void kernel_launch(void* const* d_in, const int* in_sizes, int n_in,
                              void* d_out, int out_size)
{
    const float* x  = (const float*)d_in[0];  // [B, C, M, N]
    const float* W  = (const float*)d_in[1];  // [1, C, M, 1] -> 128 floats
    const float* rt = (const float*)d_in[2];  // [64]
    const float* dt = (const float*)d_in[3];  // [64]
    float* out = (float*)d_out;

    dim3 grid(NN / (256 * 4), BB);
    conv_kernel<<<grid, 256>>>(x, W, out);
    tail_kernel<<<1, BB>>>(rt, dt, out + (size_t)BB * NN);
}

// round 8
// speedup vs baseline: 1.0704x; 1.0143x over previous
#include <cuda_runtime.h>
#include <math_constants.h>

// Problem constants
#define BB 256
#define CC 8
#define MM 16
#define NN 4096
#define CM 128      // CC*MM
#define LEN_R 64
#define LEN_D 64
#define NBLK 4      // blocks along N per b (NN / 1024)

// Per-(b, n-block) partial argmax scratch + per-b ticket (device globals).
// Tickets are zero-initialized at load and reset to 0 by the winning block,
// so the kernel is deterministic across graph replays.
__device__ float g_pmax[BB][NBLK];
__device__ int   g_pidx[BB][NBLK];
__device__ int   g_ticket[BB];

// Fused kernel:
//  - outputs[b,n] = sum_k x[b,k,n] * W[k]  (k = c*M+m, 128 terms)
//  - block-level partial argmax (first occurrence) -> scratch
//  - last block per b reduces partials, writes tail, resets ticket.
// tail layout (after outputs): d[B], r[B], d[B] (pytree leaves of (outputs, d, (r,d)))
__global__ __launch_bounds__(256) void fused_kernel(
    const float* __restrict__ x, const float* __restrict__ W,
    const float* __restrict__ r_target, const float* __restrict__ d_target,
    float* __restrict__ out, float* __restrict__ tail)
{
    __shared__ float w[CM];
    int t = threadIdx.x;
    if (t < CM) w[t] = W[t];
    __syncthreads();

    int b  = blockIdx.y;
    int n4 = blockIdx.x * blockDim.x + t;          // float4 lane index in N/4
    const float4* xb = reinterpret_cast<const float4*>(x) + (size_t)b * CM * (NN / 4);

    float4 acc = make_float4(0.f, 0.f, 0.f, 0.f);
    #pragma unroll 16
    for (int k = 0; k < CM; k++) {
        float4 v = xb[(size_t)k * (NN / 4) + n4];
        float wk = w[k];
        acc.x += v.x * wk;
        acc.y += v.y * wk;
        acc.z += v.z * wk;
        acc.w += v.w * wk;
    }
    reinterpret_cast<float4*>(out + (size_t)b * NN)[n4] = acc;

    // Thread-local argmax over 4 lanes (strict > keeps first occurrence).
    int nbase = n4 * 4;
    float best = acc.x; int bidx = nbase;
    if (acc.y > best) { best = acc.y; bidx = nbase + 1; }
    if (acc.z > best) { best = acc.z; bidx = nbase + 2; }
    if (acc.w > best) { best = acc.w; bidx = nbase + 3; }

    // Block reduction (first occurrence on ties).
    __shared__ float sv[256];
    __shared__ int   si[256];
    sv[t] = best; si[t] = bidx;
    __syncthreads();
    #pragma unroll
    for (int s = 128; s > 0; s >>= 1) {
        if (t < s) {
            float ov = sv[t + s]; int oi = si[t + s];
            if (ov > sv[t] || (ov == sv[t] && oi < si[t])) { sv[t] = ov; si[t] = oi; }
        }
        __syncthreads();
    }

    // Publish partial; last block per b finishes.
    __shared__ int s_last;
    if (t == 0) {
        g_pmax[b][blockIdx.x] = sv[0];
        g_pidx[b][blockIdx.x] = si[0];
        __threadfence();
        int prev = atomicAdd(&g_ticket[b], 1);
        s_last = (prev == NBLK - 1);
    }
    __syncthreads();

    if (s_last && t == 0) {
        // Winner re-reads all partials; volatile forces L2-visible loads
        // (L1 is per-SM and non-coherent for plain global loads).
        volatile float* pm = &g_pmax[b][0];
        volatile int*   pi = &g_pidx[b][0];
        float fb = pm[0];
        int   fi = pi[0];
        #pragma unroll
        for (int j = 1; j < NBLK; j++) {
            float v = pm[j]; int i = pi[j];
            if (v > fb || (v == fb && i < fi)) { fb = v; fi = i; }
        }
        int ri = fi / LEN_R;
        int di = fi - (fi / LEN_R) * LEN_D;
        // .astype(index.dtype) truncates toward zero; replicate via int cast.
        float rv = (float)(long long)(r_target[ri]);
        float dv = (float)(long long)(d_target[di]);
        tail[b]          = dv;  // leaf 2: d
        tail[BB + b]     = rv;  // leaf 3: r
        tail[2 * BB + b] = dv;  // leaf 4: d
        g_ticket[b] = 0;       // reset for next graph replay (deterministic)
    }
}

extern "C" void kernel_launch(void* const* d_in, const int* in_sizes, int n_in,
                              void* d_out, int out_size)
{
    const float* x  = (const float*)d_in[0];  // [B, C, M, N]
    const float* W  = (const float*)d_in[1];  // [1, C, M, 1] -> 128 floats
    const float* rt = (const float*)d_in[2];  // [64]
    const float* dt = (const float*)d_in[3];  // [64]
    float* out = (float*)d_out;

    dim3 grid(NN / (256 * 4), BB);
    fused_kernel<<<grid, 256>>>(x, W, rt, dt, out, out + (size_t)BB * NN);
}